// round 4
// baseline (speedup 1.0000x reference)
#include <cuda_runtime.h>

// InvertAffine: (B, 3, 4) fp32 affine shift matrices.
// inverse top-3-rows = [R, -R t], R = (I3+A)^-1 via closed-form 3x3 adjugate.
//
// Round-4: Round-2 geometry (256 matrices / 256 threads / high occupancy,
// which gave the best cross-block load/store phase overlap) + separate
// 12 KB output smem buffer (3 syncs -> 2) + __ldcs/__stcs streaming hints
// (both streams touch-once, working set >> L2).

__device__ __forceinline__ void invert3(const float4 a0, const float4 a1, const float4 a2,
                                        float4& q0, float4& q1, float4& q2)
{
    // M = I3 + A, t = last column
    const float m00 = a0.x + 1.0f, m01 = a0.y,        m02 = a0.z,        t0 = a0.w;
    const float m10 = a1.x,        m11 = a1.y + 1.0f, m12 = a1.z,        t1 = a1.w;
    const float m20 = a2.x,        m21 = a2.y,        m22 = a2.z + 1.0f, t2 = a2.w;

    const float c00 = m11 * m22 - m12 * m21;
    const float c10 = m12 * m20 - m10 * m22;
    const float c20 = m10 * m21 - m11 * m20;
    const float det = m00 * c00 + m01 * c10 + m02 * c20;
    const float rdet = 1.0f / det;

    const float i00 = c00 * rdet;
    const float i01 = (m02 * m21 - m01 * m22) * rdet;
    const float i02 = (m01 * m12 - m02 * m11) * rdet;
    const float i10 = c10 * rdet;
    const float i11 = (m00 * m22 - m02 * m20) * rdet;
    const float i12 = (m02 * m10 - m00 * m12) * rdet;
    const float i20 = c20 * rdet;
    const float i21 = (m01 * m20 - m00 * m21) * rdet;
    const float i22 = (m00 * m11 - m01 * m10) * rdet;

    const float o0 = -(i00 * t0 + i01 * t1 + i02 * t2);
    const float o1 = -(i10 * t0 + i11 * t1 + i12 * t2);
    const float o2 = -(i20 * t0 + i21 * t1 + i22 * t2);

    q0 = make_float4(i00, i01, i02, o0);
    q1 = make_float4(i10, i11, i12, o1);
    q2 = make_float4(i20, i21, i22, o2);
}

__global__ void __launch_bounds__(256, 8) invert_affine_kernel(
    const float4* __restrict__ in, float4* __restrict__ out, int b)
{
    __shared__ float4 s_in[768];   // 256 matrices * 3 float4 = 12 KB
    __shared__ float4 s_out[768];  // 12 KB (24 KB/block -> still 8 blocks/SM)

    const int t = threadIdx.x;
    const int mbase = blockIdx.x * 256;
    const long long fbase = (long long)mbase * 3;
    const int nmat = min(256, b - mbase);
    const int nf4 = nmat * 3;

    // Coalesced gmem -> smem (3 front-batched LDG.128, evict-first)
#pragma unroll
    for (int k = 0; k < 3; k++) {
        const int idx = t + k * 256;
        if (idx < nf4) s_in[idx] = __ldcs(in + fbase + idx);
    }
    __syncthreads();

    if (t < nmat) {
        float4 q0, q1, q2;
        invert3(s_in[3 * t + 0], s_in[3 * t + 1], s_in[3 * t + 2], q0, q1, q2);
        s_out[3 * t + 0] = q0;
        s_out[3 * t + 1] = q1;
        s_out[3 * t + 2] = q2;
    }
    __syncthreads();

    // Coalesced smem -> gmem (3 STG.128, streaming)
#pragma unroll
    for (int k = 0; k < 3; k++) {
        const int idx = t + k * 256;
        if (idx < nf4) __stcs(out + fbase + idx, s_out[idx]);
    }
}

extern "C" void kernel_launch(void* const* d_in, const int* in_sizes, int n_in,
                              void* d_out, int out_size)
{
    const float4* in = (const float4*)d_in[0];
    float4* out = (float4*)d_out;
    const int b = in_sizes[0] / 12;  // (B, 3, 4) fp32 -> 12 elements per matrix

    const int threads = 256;
    const int blocks = (b + 255) / 256;
    invert_affine_kernel<<<blocks, threads>>>(in, out, b);
}

// round 5
// speedup vs baseline: 1.1380x; 1.1380x over previous
#include <cuda_runtime.h>

// InvertAffine: (B, 3, 4) fp32 affine shift matrices.
// inverse top-3-rows = [R, -R t], R = (I3+A)^-1 via closed-form 3x3 adjugate.
//
// Round-5: Round-3 geometry (512 matrices/block, 2 per thread, separate
// in/out smem buffers, 2 syncs, 6 front-batched coalesced LDG.128/thread)
// with the __ldcs/__stcs streaming hints REMOVED — R2 vs R4 isolated the
// hints (especially evict-first stores) as an ~8.5 us regression on sm_103a.

__device__ __forceinline__ void invert3(const float4 a0, const float4 a1, const float4 a2,
                                        float4& q0, float4& q1, float4& q2)
{
    // M = I3 + A, t = last column
    const float m00 = a0.x + 1.0f, m01 = a0.y,        m02 = a0.z,        t0 = a0.w;
    const float m10 = a1.x,        m11 = a1.y + 1.0f, m12 = a1.z,        t1 = a1.w;
    const float m20 = a2.x,        m21 = a2.y,        m22 = a2.z + 1.0f, t2 = a2.w;

    const float c00 = m11 * m22 - m12 * m21;
    const float c10 = m12 * m20 - m10 * m22;
    const float c20 = m10 * m21 - m11 * m20;
    const float det = m00 * c00 + m01 * c10 + m02 * c20;
    const float rdet = 1.0f / det;

    const float i00 = c00 * rdet;
    const float i01 = (m02 * m21 - m01 * m22) * rdet;
    const float i02 = (m01 * m12 - m02 * m11) * rdet;
    const float i10 = c10 * rdet;
    const float i11 = (m00 * m22 - m02 * m20) * rdet;
    const float i12 = (m02 * m10 - m00 * m12) * rdet;
    const float i20 = c20 * rdet;
    const float i21 = (m01 * m20 - m00 * m21) * rdet;
    const float i22 = (m00 * m11 - m01 * m10) * rdet;

    const float o0 = -(i00 * t0 + i01 * t1 + i02 * t2);
    const float o1 = -(i10 * t0 + i11 * t1 + i12 * t2);
    const float o2 = -(i20 * t0 + i21 * t1 + i22 * t2);

    q0 = make_float4(i00, i01, i02, o0);
    q1 = make_float4(i10, i11, i12, o1);
    q2 = make_float4(i20, i21, i22, o2);
}

__global__ void __launch_bounds__(256) invert_affine_kernel(
    const float4* __restrict__ in, float4* __restrict__ out, int b)
{
    __shared__ float4 s_in[1536];   // 512 matrices * 3 float4 = 24 KB
    __shared__ float4 s_out[1536];  // 24 KB

    const int t = threadIdx.x;
    const int mbase = blockIdx.x * 512;
    const long long fbase = (long long)mbase * 3;
    const int nmat = min(512, b - mbase);
    const int nf4 = nmat * 3;

    // Coalesced gmem -> smem: 6 front-batched LDG.128 per thread
#pragma unroll
    for (int k = 0; k < 6; k++) {
        const int idx = t + k * 256;
        if (idx < nf4) s_in[idx] = in[fbase + idx];
    }
    __syncthreads();

    // Each thread inverts 2 matrices into the separate out buffer
#pragma unroll
    for (int m = 0; m < 2; m++) {
        const int mi = t + m * 256;
        if (mi < nmat) {
            float4 q0, q1, q2;
            invert3(s_in[3 * mi + 0], s_in[3 * mi + 1], s_in[3 * mi + 2], q0, q1, q2);
            s_out[3 * mi + 0] = q0;
            s_out[3 * mi + 1] = q1;
            s_out[3 * mi + 2] = q2;
        }
    }
    __syncthreads();

    // Coalesced smem -> gmem
#pragma unroll
    for (int k = 0; k < 6; k++) {
        const int idx = t + k * 256;
        if (idx < nf4) out[fbase + idx] = s_out[idx];
    }
}

extern "C" void kernel_launch(void* const* d_in, const int* in_sizes, int n_in,
                              void* d_out, int out_size)
{
    const float4* in = (const float4*)d_in[0];
    float4* out = (float4*)d_out;
    const int b = in_sizes[0] / 12;  // (B, 3, 4) fp32 -> 12 elements per matrix

    const int threads = 256;
    const int blocks = (b + 511) / 512;
    invert_affine_kernel<<<blocks, threads>>>(in, out, b);
}